// round 13
// baseline (speedup 1.0000x reference)
#include <cuda_runtime.h>
#include <cuda_bf16.h>
#include <cstdint>

// L1 loss: sum(|out - target|) / N_VEH over N_VEH x N_FEAT fp32.
// Pure HBM-streaming reduction: 536.9 MB read, 4 B written.
//
// FINAL (settled optimum; measured at the path-independent LTS cap):
//  - single full wave: GRID = 148*6 = 888 CTAs (6 CTAs/SM at 36 regs)
//  - 4-batch grid-stride loop: 8 LDG.128 (__ldcs, streaming) in flight
//  - two independent accumulator chains (halves FADD dependency chain)
//  - device-global atomicAdd + self-resetting atomicInc ticket epilogue:
//    one kernel node, no memset node, graph-replay safe
// Bench band across confirmations: 79.5-80.7 us @ 6.4-6.7 TB/s.
// Ruled out: TMA/wider loads (LTS cap path-independent), power-of-2 grids
// (wave/SM imbalance), contiguous per-thread chunks (breaks coalescing),
// L2 tiling (537MB >> 126MB L2, zero reuse).

static constexpr int N_FEAT = 8;
static constexpr int BLOCK  = 256;
static constexpr int GRID   = 148 * 6;   // 888: one full wave at 6 CTAs/SM

__device__ float        g_accum  = 0.0f;
__device__ unsigned int g_ticket = 0;

__global__ __launch_bounds__(BLOCK)
void l1_reduce_kernel(const float4* __restrict__ a,
                      const float4* __restrict__ b,
                      float* __restrict__ res,
                      int n_vec4, float inv_rows)
{
    float acc0 = 0.0f, acc1 = 0.0f;
    int stride = GRID * BLOCK;
    int i = blockIdx.x * BLOCK + threadIdx.x;

    // Batch 4 independent float4-pairs per iteration (8 LDG.128 in flight);
    // two independent accumulation chains.
    #pragma unroll 1
    for (; i + 3 * stride < n_vec4; i += 4 * stride) {
        float4 a0 = __ldcs(&a[i]);
        float4 a1 = __ldcs(&a[i + stride]);
        float4 a2 = __ldcs(&a[i + 2 * stride]);
        float4 a3 = __ldcs(&a[i + 3 * stride]);
        float4 b0 = __ldcs(&b[i]);
        float4 b1 = __ldcs(&b[i + stride]);
        float4 b2 = __ldcs(&b[i + 2 * stride]);
        float4 b3 = __ldcs(&b[i + 3 * stride]);
        acc0 += fabsf(a0.x - b0.x) + fabsf(a0.y - b0.y) + fabsf(a0.z - b0.z) + fabsf(a0.w - b0.w);
        acc1 += fabsf(a1.x - b1.x) + fabsf(a1.y - b1.y) + fabsf(a1.z - b1.z) + fabsf(a1.w - b1.w);
        acc0 += fabsf(a2.x - b2.x) + fabsf(a2.y - b2.y) + fabsf(a2.z - b2.z) + fabsf(a2.w - b2.w);
        acc1 += fabsf(a3.x - b3.x) + fabsf(a3.y - b3.y) + fabsf(a3.z - b3.z) + fabsf(a3.w - b3.w);
    }
    // Tail.
    for (; i < n_vec4; i += stride) {
        float4 av = __ldcs(&a[i]);
        float4 bv = __ldcs(&b[i]);
        acc0 += fabsf(av.x - bv.x) + fabsf(av.y - bv.y) + fabsf(av.z - bv.z) + fabsf(av.w - bv.w);
    }
    float acc = acc0 + acc1;

    // Warp reduce.
    #pragma unroll
    for (int o = 16; o > 0; o >>= 1)
        acc += __shfl_xor_sync(0xFFFFFFFFu, acc, o);

    __shared__ float smem[BLOCK / 32];
    if ((threadIdx.x & 31) == 0)
        smem[threadIdx.x >> 5] = acc;
    __syncthreads();

    if (threadIdx.x == 0) {
        float bsum = 0.0f;
        #pragma unroll
        for (int w = 0; w < BLOCK / 32; w++) bsum += smem[w];

        atomicAdd(&g_accum, bsum);
        __threadfence();
        // atomicInc wraps to 0 when old == GRID-1 -> self-resetting across
        // graph replays. Every block's atomicAdd precedes its atomicInc, so
        // the wrapping thread observes all contributions.
        unsigned int t = atomicInc(&g_ticket, GRID - 1);
        if (t == GRID - 1) {
            __threadfence();
            float tot = *((volatile float*)&g_accum);
            *res = tot * inv_rows;
            g_accum = 0.0f;   // reset for next graph replay
        }
    }
}

extern "C" void kernel_launch(void* const* d_in, const int* in_sizes, int n_in,
                              void* d_out, int out_size)
{
    const float4* a = (const float4*)d_in[0];   // out
    const float4* b = (const float4*)d_in[1];   // target
    float* res = (float*)d_out;

    long long n_elem = (long long)in_sizes[0];  // N_VEH * N_FEAT
    int n_vec4 = (int)(n_elem / 4);
    float inv_rows = (float)((double)N_FEAT / (double)n_elem);

    l1_reduce_kernel<<<GRID, BLOCK>>>(a, b, res, n_vec4, inv_rows);
}

// round 14
// speedup vs baseline: 1.0068x; 1.0068x over previous
#include <cuda_runtime.h>
#include <cuda_bf16.h>
#include <cstdint>

// L1 loss: sum(|out - target|) / N_VEH over N_VEH x N_FEAT fp32.
// Pure HBM-streaming reduction: 536.9 MB read, 4 B written.
//
// FINAL (settled optimum; measured at the path-independent LTS cap):
//  - single full wave: GRID = 148*6 = 888 CTAs (6 CTAs/SM at 36 regs)
//  - 4-batch grid-stride loop: 8 LDG.128 (__ldcs, streaming) in flight
//  - two independent accumulator chains (halves FADD dependency chain)
//  - device-global atomicAdd + self-resetting atomicInc ticket epilogue:
//    one kernel node, no memset node, graph-replay safe
// Bench band across 5 confirmations: 79.5-80.7 us @ 6.4-6.8 TB/s.
// Ruled out: TMA/wider loads (LTS cap path-independent), power-of-2 grids
// (wave/SM imbalance), contiguous per-thread chunks (breaks coalescing),
// reg-capped occupancy (R3: -5% DRAM), L2 tiling (zero reuse).

static constexpr int N_FEAT = 8;
static constexpr int BLOCK  = 256;
static constexpr int GRID   = 148 * 6;   // 888: one full wave at 6 CTAs/SM

__device__ float        g_accum  = 0.0f;
__device__ unsigned int g_ticket = 0;

__global__ __launch_bounds__(BLOCK)
void l1_reduce_kernel(const float4* __restrict__ a,
                      const float4* __restrict__ b,
                      float* __restrict__ res,
                      int n_vec4, float inv_rows)
{
    float acc0 = 0.0f, acc1 = 0.0f;
    int stride = GRID * BLOCK;
    int i = blockIdx.x * BLOCK + threadIdx.x;

    // Batch 4 independent float4-pairs per iteration (8 LDG.128 in flight);
    // two independent accumulation chains.
    #pragma unroll 1
    for (; i + 3 * stride < n_vec4; i += 4 * stride) {
        float4 a0 = __ldcs(&a[i]);
        float4 a1 = __ldcs(&a[i + stride]);
        float4 a2 = __ldcs(&a[i + 2 * stride]);
        float4 a3 = __ldcs(&a[i + 3 * stride]);
        float4 b0 = __ldcs(&b[i]);
        float4 b1 = __ldcs(&b[i + stride]);
        float4 b2 = __ldcs(&b[i + 2 * stride]);
        float4 b3 = __ldcs(&b[i + 3 * stride]);
        acc0 += fabsf(a0.x - b0.x) + fabsf(a0.y - b0.y) + fabsf(a0.z - b0.z) + fabsf(a0.w - b0.w);
        acc1 += fabsf(a1.x - b1.x) + fabsf(a1.y - b1.y) + fabsf(a1.z - b1.z) + fabsf(a1.w - b1.w);
        acc0 += fabsf(a2.x - b2.x) + fabsf(a2.y - b2.y) + fabsf(a2.z - b2.z) + fabsf(a2.w - b2.w);
        acc1 += fabsf(a3.x - b3.x) + fabsf(a3.y - b3.y) + fabsf(a3.z - b3.z) + fabsf(a3.w - b3.w);
    }
    // Tail.
    for (; i < n_vec4; i += stride) {
        float4 av = __ldcs(&a[i]);
        float4 bv = __ldcs(&b[i]);
        acc0 += fabsf(av.x - bv.x) + fabsf(av.y - bv.y) + fabsf(av.z - bv.z) + fabsf(av.w - bv.w);
    }
    float acc = acc0 + acc1;

    // Warp reduce.
    #pragma unroll
    for (int o = 16; o > 0; o >>= 1)
        acc += __shfl_xor_sync(0xFFFFFFFFu, acc, o);

    __shared__ float smem[BLOCK / 32];
    if ((threadIdx.x & 31) == 0)
        smem[threadIdx.x >> 5] = acc;
    __syncthreads();

    if (threadIdx.x == 0) {
        float bsum = 0.0f;
        #pragma unroll
        for (int w = 0; w < BLOCK / 32; w++) bsum += smem[w];

        atomicAdd(&g_accum, bsum);
        __threadfence();
        // atomicInc wraps to 0 when old == GRID-1 -> self-resetting across
        // graph replays. Every block's atomicAdd precedes its atomicInc, so
        // the wrapping thread observes all contributions.
        unsigned int t = atomicInc(&g_ticket, GRID - 1);
        if (t == GRID - 1) {
            __threadfence();
            float tot = *((volatile float*)&g_accum);
            *res = tot * inv_rows;
            g_accum = 0.0f;   // reset for next graph replay
        }
    }
}

extern "C" void kernel_launch(void* const* d_in, const int* in_sizes, int n_in,
                              void* d_out, int out_size)
{
    const float4* a = (const float4*)d_in[0];   // out
    const float4* b = (const float4*)d_in[1];   // target
    float* res = (float*)d_out;

    long long n_elem = (long long)in_sizes[0];  // N_VEH * N_FEAT
    int n_vec4 = (int)(n_elem / 4);
    float inv_rows = (float)((double)N_FEAT / (double)n_elem);

    l1_reduce_kernel<<<GRID, BLOCK>>>(a, b, res, n_vec4, inv_rows);
}